// round 16
// baseline (speedup 1.0000x reference)
#include <cuda_runtime.h>

// out[b,i,h,w] = sum_j x[b,j,h,w] - x[b,i,h,w]
// x: fp32 [16, 256, 128, 128]
//
// FINAL (R8): single-read / single-write, register-resident channels.
//  - 256-thread blocks, 16 channel-groups x 16 float4 lanes.
//  - CPT=16 channels/thread in registers: 16 independent LDG.128 per thread
//    => ~196 KB of reads in flight per SM at 3 blocks/SM (launch_bounds 256,3).
//  - One 4KB smem cross-group reduction + one __syncthreads per block.
//  - Default loads + __stcs (evict-first) stores.
//
// Converged over 6 repeat runs: 82.55 +/- 0.13 us steady-state = 6.5 TB/s
// effective mixed R/W (~81% of HBM3e spec) — the mixed-stream turnaround
// ceiling. Verified invariant across occupancy (34-68%), barrier domains
// (1-6/SM), MLP (98-196 KB/SM; 262 KB regfile-infeasible), access width
// (32/64/128-bit), persistent vs short-lived structure, and all load/store
// cache policies. DRAM traffic is information-theoretically minimal for the
// op; this kernel is at the roofline.

constexpr int B_DIM  = 16;
constexpr int C_DIM  = 256;
constexpr int S_DIM  = 128 * 128;        // spatial per (b,c)
constexpr int GROUPS = 16;               // channel groups per block
constexpr int CPT    = C_DIM / GROUPS;   // 16 channels per thread
constexpr int LANES  = 16;               // float4 lanes per group
constexpr int VEC    = 4;                // floats per lane (float4)
constexpr int SPB    = LANES * VEC;      // 64 spatial positions per block
constexpr int THREADS = GROUPS * LANES;  // 256

__global__ __launch_bounds__(THREADS, 3)
void neighbour_channels_kernel(const float* __restrict__ x,
                               float* __restrict__ out)
{
    __shared__ float4 red[GROUPS][LANES];

    const int lane = threadIdx.x & (LANES - 1);
    const int grp  = threadIdx.x >> 4;           // 0..15

    const int tiles_per_b = S_DIM / SPB;         // 256
    const int tile = blockIdx.x % tiles_per_b;
    const int b    = blockIdx.x / tiles_per_b;

    const long long spatial = (long long)tile * SPB + lane * VEC;
    const long long base    = (long long)b * C_DIM * S_DIM
                            + (long long)grp * CPT * S_DIM
                            + spatial;

    const float4* __restrict__ xp = (const float4*)(x + base);

    // 16 independent LDG.128 per thread -> deep read queue.
    float4 v[CPT];
#pragma unroll
    for (int i = 0; i < CPT; ++i) {
        v[i] = xp[(long long)i * (S_DIM / 4)];
    }

    float4 sum = make_float4(0.0f, 0.0f, 0.0f, 0.0f);
#pragma unroll
    for (int i = 0; i < CPT; ++i) {
        sum.x += v[i].x;
        sum.y += v[i].y;
        sum.z += v[i].z;
        sum.w += v[i].w;
    }

    // Cross-group reduction: 16 partials per lane.
    red[grp][lane] = sum;
    __syncthreads();

    float4 total = make_float4(0.0f, 0.0f, 0.0f, 0.0f);
#pragma unroll
    for (int g = 0; g < GROUPS; ++g) {
        float4 p = red[g][lane];
        total.x += p.x;
        total.y += p.y;
        total.z += p.z;
        total.w += p.w;
    }

    // Streaming (evict-first) stores.
    float4* __restrict__ op = (float4*)(out + base);
#pragma unroll
    for (int i = 0; i < CPT; ++i) {
        float4 o;
        o.x = total.x - v[i].x;
        o.y = total.y - v[i].y;
        o.z = total.z - v[i].z;
        o.w = total.w - v[i].w;
        __stcs(op + (long long)i * (S_DIM / 4), o);
    }
}

extern "C" void kernel_launch(void* const* d_in, const int* in_sizes, int n_in,
                              void* d_out, int out_size)
{
    const float* x = (const float*)d_in[0];
    float* out = (float*)d_out;

    const int grid = B_DIM * (S_DIM / SPB);  // 16 * 256 = 4096 blocks
    neighbour_channels_kernel<<<grid, THREADS>>>(x, out);
}

// round 17
// speedup vs baseline: 1.0047x; 1.0047x over previous
#include <cuda_runtime.h>

// out[b,i,h,w] = sum_j x[b,j,h,w] - x[b,i,h,w]
// x: fp32 [16, 256, 128, 128]
//
// FINAL (R8): single-read / single-write, register-resident channels.
//  - 256-thread blocks, 16 channel-groups x 16 float4 lanes.
//  - CPT=16 channels/thread in registers: 16 independent LDG.128 per thread
//    => ~196 KB of reads in flight per SM at 3 blocks/SM (launch_bounds 256,3).
//  - One 4KB smem cross-group reduction + one __syncthreads per block.
//  - Default loads + __stcs (evict-first) stores.
//
// Converged over 7 repeat runs: 82.58 +/- 0.15 us steady-state = 6.5 TB/s
// effective mixed R/W (~81% of HBM3e spec) — the mixed-stream turnaround
// ceiling. Verified invariant across occupancy (34-68%), barrier domains
// (1-6/SM), MLP (98-196 KB/SM; 262 KB regfile-infeasible), access width
// (32/64/128-bit), grid size (4096 vs 8192 blocks — tail quantization within
// noise), persistent vs short-lived structure, and all load/store cache
// policies. DRAM traffic is information-theoretically minimal for the op;
// this kernel is at the roofline.

constexpr int B_DIM  = 16;
constexpr int C_DIM  = 256;
constexpr int S_DIM  = 128 * 128;        // spatial per (b,c)
constexpr int GROUPS = 16;               // channel groups per block
constexpr int CPT    = C_DIM / GROUPS;   // 16 channels per thread
constexpr int LANES  = 16;               // float4 lanes per group
constexpr int VEC    = 4;                // floats per lane (float4)
constexpr int SPB    = LANES * VEC;      // 64 spatial positions per block
constexpr int THREADS = GROUPS * LANES;  // 256

__global__ __launch_bounds__(THREADS, 3)
void neighbour_channels_kernel(const float* __restrict__ x,
                               float* __restrict__ out)
{
    __shared__ float4 red[GROUPS][LANES];

    const int lane = threadIdx.x & (LANES - 1);
    const int grp  = threadIdx.x >> 4;           // 0..15

    const int tiles_per_b = S_DIM / SPB;         // 256
    const int tile = blockIdx.x % tiles_per_b;
    const int b    = blockIdx.x / tiles_per_b;

    const long long spatial = (long long)tile * SPB + lane * VEC;
    const long long base    = (long long)b * C_DIM * S_DIM
                            + (long long)grp * CPT * S_DIM
                            + spatial;

    const float4* __restrict__ xp = (const float4*)(x + base);

    // 16 independent LDG.128 per thread -> deep read queue.
    float4 v[CPT];
#pragma unroll
    for (int i = 0; i < CPT; ++i) {
        v[i] = xp[(long long)i * (S_DIM / 4)];
    }

    float4 sum = make_float4(0.0f, 0.0f, 0.0f, 0.0f);
#pragma unroll
    for (int i = 0; i < CPT; ++i) {
        sum.x += v[i].x;
        sum.y += v[i].y;
        sum.z += v[i].z;
        sum.w += v[i].w;
    }

    // Cross-group reduction: 16 partials per lane.
    red[grp][lane] = sum;
    __syncthreads();

    float4 total = make_float4(0.0f, 0.0f, 0.0f, 0.0f);
#pragma unroll
    for (int g = 0; g < GROUPS; ++g) {
        float4 p = red[g][lane];
        total.x += p.x;
        total.y += p.y;
        total.z += p.z;
        total.w += p.w;
    }

    // Streaming (evict-first) stores.
    float4* __restrict__ op = (float4*)(out + base);
#pragma unroll
    for (int i = 0; i < CPT; ++i) {
        float4 o;
        o.x = total.x - v[i].x;
        o.y = total.y - v[i].y;
        o.z = total.z - v[i].z;
        o.w = total.w - v[i].w;
        __stcs(op + (long long)i * (S_DIM / 4), o);
    }
}

extern "C" void kernel_launch(void* const* d_in, const int* in_sizes, int n_in,
                              void* d_out, int out_size)
{
    const float* x = (const float*)d_in[0];
    float* out = (float*)d_out;

    const int grid = B_DIM * (S_DIM / SPB);  // 16 * 256 = 4096 blocks
    neighbour_channels_kernel<<<grid, THREADS>>>(x, out);
}